// round 1
// baseline (speedup 1.0000x reference)
#include <cuda_runtime.h>

#define BATCH 32
#define DIM 96
#define HH 128
#define WW 128
#define CR 24            // DIM / 4
#define KK 9             // 3x3
#define PLANE_ELEMS (HH * WW)          // 16384
#define PLANE_F4 (PLANE_ELEMS / 4)     // 4096
#define NPLANES (BATCH * DIM)          // 3072
#define BN_EPS 1e-5f

// scratch (no allocations allowed)
__device__ float g_pooled[NPLANES];          // [b][c] mean
__device__ float g_wdyn[NPLANES * KK];       // [b][c][3][3]

// ---------------------------------------------------------------------------
// Kernel 1: global average pool per (b,c) plane. One block per plane.
// ---------------------------------------------------------------------------
__global__ void pool_kernel(const float* __restrict__ x) {
    const int plane = blockIdx.x;
    const float4* __restrict__ x4 = (const float4*)(x) + (size_t)plane * PLANE_F4;
    const int tid = threadIdx.x;

    float acc = 0.f;
#pragma unroll 4
    for (int i = tid; i < PLANE_F4; i += 256) {
        float4 v = x4[i];
        acc += (v.x + v.y) + (v.z + v.w);
    }
    // warp reduce
#pragma unroll
    for (int off = 16; off > 0; off >>= 1)
        acc += __shfl_xor_sync(0xffffffffu, acc, off);

    __shared__ float warp_sums[8];
    if ((tid & 31) == 0) warp_sums[tid >> 5] = acc;
    __syncthreads();
    if (tid == 0) {
        float s = 0.f;
#pragma unroll
        for (int w = 0; w < 8; w++) s += warp_sums[w];
        g_pooled[plane] = s * (1.0f / (float)PLANE_ELEMS);
    }
}

// ---------------------------------------------------------------------------
// Kernel 2: dynamic weight generation. One block per batch sample.
//   h1 = sigmoid(BN(pooled @ w1^T));  wdyn = h1 @ w2^T + b2
// ---------------------------------------------------------------------------
__global__ void weight_kernel(const float* __restrict__ w1,      // [CR, DIM]
                              const float* __restrict__ gamma,   // [CR]
                              const float* __restrict__ beta,    // [CR]
                              const float* __restrict__ rmean,   // [CR]
                              const float* __restrict__ rvar,    // [CR]
                              const float* __restrict__ w2,      // [DIM*KK, CR]
                              const float* __restrict__ b2) {    // [DIM*KK]
    const int b = blockIdx.x;
    const int tid = threadIdx.x;   // 128 threads

    __shared__ float pooled_s[DIM];
    __shared__ float h1_s[CR];

    if (tid < DIM) pooled_s[tid] = g_pooled[b * DIM + tid];
    __syncthreads();

    if (tid < CR) {
        float acc = 0.f;
        const float* wrow = w1 + tid * DIM;
#pragma unroll 8
        for (int i = 0; i < DIM; i++) acc += pooled_s[i] * wrow[i];
        // BatchNorm (inference) + sigmoid
        float z = (acc - rmean[tid]) * rsqrtf(rvar[tid] + BN_EPS) * gamma[tid] + beta[tid];
        h1_s[tid] = 1.0f / (1.0f + __expf(-z));
    }
    __syncthreads();

    const int nout = DIM * KK;  // 864
    for (int o = tid; o < nout; o += 128) {
        const float* wrow = w2 + o * CR;
        float acc = b2[o];
#pragma unroll
        for (int i = 0; i < CR; i++) acc += h1_s[i] * wrow[i];
        g_wdyn[b * nout + o] = acc;
    }
}

// ---------------------------------------------------------------------------
// Kernel 3: per-sample depthwise 3x3, stride 1, pad 1.
// One block per (plane, 32-row tile). Smem tile (34 rows x 130 cols, +1 col
// shift so col halo is explicit zeros).
// ---------------------------------------------------------------------------
#define TILE_H 32
#define SROWS (TILE_H + 2)
#define SPITCH 132   // 130 used, padded

__global__ __launch_bounds__(256) void dwconv_kernel(const float* __restrict__ x,
                                                     const float* __restrict__ bias,
                                                     float* __restrict__ out) {
    const int plane = blockIdx.x;            // b*DIM + c
    const int c = plane % DIM;
    const int row0 = blockIdx.y * TILE_H;

    __shared__ float s[SROWS][SPITCH];
    __shared__ float wsh[KK];

    const int tid = threadIdx.x;             // 256
    if (tid < KK) wsh[tid] = g_wdyn[plane * KK + tid];
    // zero the column halo
    if (tid >= 16 && tid < 16 + SROWS) s[tid - 16][0] = 0.f;
    if (tid >= 64 && tid < 64 + SROWS) s[tid - 64][129] = 0.f;

    const float4* __restrict__ x4 = (const float4*)(x) + (size_t)plane * PLANE_F4;

    // load 34 rows x 32 float4 = 1088 float4 loads
#pragma unroll
    for (int i = tid; i < SROWS * 32; i += 256) {
        const int sr = i >> 5;
        const int c4 = i & 31;
        const int r_in = row0 + sr - 1;
        float4 v = make_float4(0.f, 0.f, 0.f, 0.f);
        if (r_in >= 0 && r_in < HH) v = x4[r_in * 32 + c4];
        float* dst = &s[sr][1 + 4 * c4];
        dst[0] = v.x; dst[1] = v.y; dst[2] = v.z; dst[3] = v.w;
    }
    __syncthreads();

    const float w00 = wsh[0], w01 = wsh[1], w02 = wsh[2];
    const float w10 = wsh[3], w11 = wsh[4], w12 = wsh[5];
    const float w20 = wsh[6], w21 = wsh[7], w22 = wsh[8];
    const float bv = bias[c];

    const int tx = tid & 31;     // float4 column
    const int ty = tid >> 5;     // 0..7
    float4* __restrict__ out4 = (float4*)(out) + (size_t)plane * PLANE_F4;

#pragma unroll
    for (int rr = ty; rr < TILE_H; rr += 8) {
        float a0[6], a1[6], a2[6];
#pragma unroll
        for (int k = 0; k < 6; k++) {
            a0[k] = s[rr + 0][4 * tx + k];
            a1[k] = s[rr + 1][4 * tx + k];
            a2[k] = s[rr + 2][4 * tx + k];
        }
        float4 o;
        float* op = &o.x;
#pragma unroll
        for (int q = 0; q < 4; q++) {
            float acc = bv;
            acc += w00 * a0[q]     + w01 * a0[q + 1] + w02 * a0[q + 2];
            acc += w10 * a1[q]     + w11 * a1[q + 1] + w12 * a1[q + 2];
            acc += w20 * a2[q]     + w21 * a2[q + 1] + w22 * a2[q + 2];
            op[q] = acc;
        }
        out4[(row0 + rr) * 32 + tx] = o;
    }
}

// ---------------------------------------------------------------------------
extern "C" void kernel_launch(void* const* d_in, const int* in_sizes, int n_in,
                              void* d_out, int out_size) {
    const float* x     = (const float*)d_in[0];
    const float* w1    = (const float*)d_in[1];
    const float* gamma = (const float*)d_in[2];
    const float* beta  = (const float*)d_in[3];
    const float* rmean = (const float*)d_in[4];
    const float* rvar  = (const float*)d_in[5];
    const float* w2    = (const float*)d_in[6];
    const float* b2    = (const float*)d_in[7];
    const float* bias  = (const float*)d_in[8];
    float* out = (float*)d_out;

    pool_kernel<<<NPLANES, 256>>>(x);
    weight_kernel<<<BATCH, 128>>>(w1, gamma, beta, rmean, rvar, w2, b2);
    dim3 grid(NPLANES, HH / TILE_H);
    dwconv_kernel<<<grid, 256>>>(x, bias, out);
}

// round 2
// speedup vs baseline: 1.1009x; 1.1009x over previous
#include <cuda_runtime.h>

#define BATCH 32
#define DIM 96
#define HH 128
#define WW 128
#define CR 24            // DIM / 4
#define KK 9             // 3x3
#define PLANE_ELEMS (HH * WW)          // 16384
#define PLANE_F4 (PLANE_ELEMS / 4)     // 4096
#define NPLANES (BATCH * DIM)          // 3072
#define BN_EPS 1e-5f

// scratch (no allocations allowed)
__device__ float g_pooled[NPLANES];          // [b][c] mean
__device__ float g_wdyn[NPLANES * KK];       // [b][c][3][3]

// ---------------------------------------------------------------------------
// Kernel 1: global average pool per (b,c) plane. One block per plane.
// ---------------------------------------------------------------------------
__global__ void pool_kernel(const float* __restrict__ x) {
    const int plane = blockIdx.x;
    const float4* __restrict__ x4 = (const float4*)(x) + (size_t)plane * PLANE_F4;
    const int tid = threadIdx.x;

    float acc = 0.f;
#pragma unroll 4
    for (int i = tid; i < PLANE_F4; i += 256) {
        float4 v = x4[i];
        acc += (v.x + v.y) + (v.z + v.w);
    }
#pragma unroll
    for (int off = 16; off > 0; off >>= 1)
        acc += __shfl_xor_sync(0xffffffffu, acc, off);

    __shared__ float warp_sums[8];
    if ((tid & 31) == 0) warp_sums[tid >> 5] = acc;
    __syncthreads();
    if (tid == 0) {
        float s = 0.f;
#pragma unroll
        for (int w = 0; w < 8; w++) s += warp_sums[w];
        g_pooled[plane] = s * (1.0f / (float)PLANE_ELEMS);
    }
}

// ---------------------------------------------------------------------------
// Kernel 2: dynamic weight generation. One block per batch sample.
// ---------------------------------------------------------------------------
__global__ void weight_kernel(const float* __restrict__ w1,      // [CR, DIM]
                              const float* __restrict__ gamma,
                              const float* __restrict__ beta,
                              const float* __restrict__ rmean,
                              const float* __restrict__ rvar,
                              const float* __restrict__ w2,      // [DIM*KK, CR]
                              const float* __restrict__ b2) {
    const int b = blockIdx.x;
    const int tid = threadIdx.x;   // 128 threads

    __shared__ float pooled_s[DIM];
    __shared__ float h1_s[CR];

    if (tid < DIM) pooled_s[tid] = g_pooled[b * DIM + tid];
    __syncthreads();

    if (tid < CR) {
        float acc = 0.f;
        const float* wrow = w1 + tid * DIM;
#pragma unroll 8
        for (int i = 0; i < DIM; i++) acc += pooled_s[i] * wrow[i];
        float z = (acc - rmean[tid]) * rsqrtf(rvar[tid] + BN_EPS) * gamma[tid] + beta[tid];
        h1_s[tid] = 1.0f / (1.0f + __expf(-z));
    }
    __syncthreads();

    const int nout = DIM * KK;  // 864
    for (int o = tid; o < nout; o += 128) {
        const float* wrow = w2 + o * CR;
        float acc = b2[o];
#pragma unroll
        for (int i = 0; i < CR; i++) acc += h1_s[i] * wrow[i];
        g_wdyn[b * nout + o] = acc;
    }
}

// ---------------------------------------------------------------------------
// Kernel 3: per-sample depthwise 3x3, stride 1, pad 1.
// Tile = full width (128) x 64 rows. Block 256 threads:
//   tx = tid&31 owns the 4-col strip [4tx, 4tx+4); ty = tid>>5 owns 8 rows.
// Smem holds 66 rows x 128 cols (row halo only; column halo via SHFL, and the
// lane-0/31 edges are the true zero pad). All smem accesses are LDS.128/STS.128
// conflict-free. Sliding 3-row register window: each smem row read once/thread.
// ---------------------------------------------------------------------------
#define TILE_H 64
#define SROWS (TILE_H + 2)   // 66

__global__ __launch_bounds__(256) void dwconv_kernel(const float* __restrict__ x,
                                                     const float* __restrict__ bias,
                                                     float* __restrict__ out) {
    const int plane = blockIdx.x;            // b*DIM + c
    const int c = plane % DIM;
    const int row0 = blockIdx.y * TILE_H;

    __shared__ float4 s4[SROWS * 32];        // 66 rows x 32 float4 = 33792 B
    __shared__ float wsh[KK];

    const int tid = threadIdx.x;             // 256
    if (tid < KK) wsh[tid] = g_wdyn[plane * KK + tid];

    const float4* __restrict__ x4 = (const float4*)(x) + (size_t)plane * PLANE_F4;

    // stage 66 rows x 32 float4 (2112 loads / 256 threads)
#pragma unroll
    for (int i = tid; i < SROWS * 32; i += 256) {
        const int sr = i >> 5;
        const int c4 = i & 31;
        const int r_in = row0 + sr - 1;
        float4 v = make_float4(0.f, 0.f, 0.f, 0.f);
        if (r_in >= 0 && r_in < HH) v = x4[r_in * 32 + c4];
        s4[i] = v;
    }
    __syncthreads();

    const float w00 = wsh[0], w01 = wsh[1], w02 = wsh[2];
    const float w10 = wsh[3], w11 = wsh[4], w12 = wsh[5];
    const float w20 = wsh[6], w21 = wsh[7], w22 = wsh[8];
    const float bv = bias[c];

    const int tx = tid & 31;     // float4 column
    const int ty = tid >> 5;     // 0..7, 8 output rows each
    const int r0 = ty * 8;       // first output row within tile
    float4* __restrict__ out4 = (float4*)(out) + (size_t)plane * PLANE_F4;

    // sliding window rows A (rr), B (rr+1), C (rr+2) in smem-row coords
    float4 vA = s4[(r0 + 0) * 32 + tx];
    float4 vB = s4[(r0 + 1) * 32 + tx];
    float lA = __shfl_up_sync(0xffffffffu, vA.w, 1);
    float rA = __shfl_down_sync(0xffffffffu, vA.x, 1);
    float lB = __shfl_up_sync(0xffffffffu, vB.w, 1);
    float rB = __shfl_down_sync(0xffffffffu, vB.x, 1);
    if (tx == 0)  { lA = 0.f; lB = 0.f; }
    if (tx == 31) { rA = 0.f; rB = 0.f; }

#pragma unroll
    for (int i = 0; i < 8; i++) {
        float4 vC = s4[(r0 + 2 + i) * 32 + tx];
        float lC = __shfl_up_sync(0xffffffffu, vC.w, 1);
        float rC = __shfl_down_sync(0xffffffffu, vC.x, 1);
        if (tx == 0)  lC = 0.f;
        if (tx == 31) rC = 0.f;

        float4 o;
        o.x = bv + w00 * lA   + w01 * vA.x + w02 * vA.y
                 + w10 * lB   + w11 * vB.x + w12 * vB.y
                 + w20 * lC   + w21 * vC.x + w22 * vC.y;
        o.y = bv + w00 * vA.x + w01 * vA.y + w02 * vA.z
                 + w10 * vB.x + w11 * vB.y + w12 * vB.z
                 + w20 * vC.x + w21 * vC.y + w22 * vC.z;
        o.z = bv + w00 * vA.y + w01 * vA.z + w02 * vA.w
                 + w10 * vB.y + w11 * vB.z + w12 * vB.w
                 + w20 * vC.y + w21 * vC.z + w22 * vC.w;
        o.w = bv + w00 * vA.z + w01 * vA.w + w02 * rA
                 + w10 * vB.z + w11 * vB.w + w12 * rB
                 + w20 * vC.z + w21 * vC.w + w22 * rC;

        out4[(row0 + r0 + i) * 32 + tx] = o;

        vA = vB; lA = lB; rA = rB;
        vB = vC; lB = lC; rB = rC;
    }
}

// ---------------------------------------------------------------------------
extern "C" void kernel_launch(void* const* d_in, const int* in_sizes, int n_in,
                              void* d_out, int out_size) {
    const float* x     = (const float*)d_in[0];
    const float* w1    = (const float*)d_in[1];
    const float* gamma = (const float*)d_in[2];
    const float* beta  = (const float*)d_in[3];
    const float* rmean = (const float*)d_in[4];
    const float* rvar  = (const float*)d_in[5];
    const float* w2    = (const float*)d_in[6];
    const float* b2    = (const float*)d_in[7];
    const float* bias  = (const float*)d_in[8];
    float* out = (float*)d_out;

    pool_kernel<<<NPLANES, 256>>>(x);
    weight_kernel<<<BATCH, 128>>>(w1, gamma, beta, rmean, rvar, w2, b2);
    dim3 grid(NPLANES, HH / TILE_H);
    dwconv_kernel<<<grid, 256>>>(x, bias, out);
}

// round 3
// speedup vs baseline: 1.1965x; 1.0869x over previous
#include <cuda_runtime.h>

#define BATCH 32
#define DIM 96
#define HH 128
#define WW 128
#define CR 24            // DIM / 4
#define KK 9             // 3x3
#define PLANE_ELEMS (HH * WW)          // 16384
#define PLANE_F4 (PLANE_ELEMS / 4)     // 4096
#define NPLANES (BATCH * DIM)          // 3072
#define BN_EPS 1e-5f

// scratch (no allocations allowed)
__device__ float g_pooled[NPLANES];          // [b][c] mean
__device__ float g_wdyn[NPLANES * KK];       // [b][c][3][3]

// ---------------------------------------------------------------------------
// Kernel 1: global average pool per (b,c) plane. One block per plane.
// (80% DRAM — at ceiling; unchanged.)
// ---------------------------------------------------------------------------
__global__ void pool_kernel(const float* __restrict__ x) {
    const int plane = blockIdx.x;
    const float4* __restrict__ x4 = (const float4*)(x) + (size_t)plane * PLANE_F4;
    const int tid = threadIdx.x;

    float acc = 0.f;
#pragma unroll 4
    for (int i = tid; i < PLANE_F4; i += 256) {
        float4 v = x4[i];
        acc += (v.x + v.y) + (v.z + v.w);
    }
#pragma unroll
    for (int off = 16; off > 0; off >>= 1)
        acc += __shfl_xor_sync(0xffffffffu, acc, off);

    __shared__ float warp_sums[8];
    if ((tid & 31) == 0) warp_sums[tid >> 5] = acc;
    __syncthreads();
    if (tid == 0) {
        float s = 0.f;
#pragma unroll
        for (int w = 0; w < 8; w++) s += warp_sums[w];
        g_pooled[plane] = s * (1.0f / (float)PLANE_ELEMS);
    }
}

// ---------------------------------------------------------------------------
// Kernel 2: dynamic weight generation. One block per batch sample.
// ---------------------------------------------------------------------------
__global__ void weight_kernel(const float* __restrict__ w1,      // [CR, DIM]
                              const float* __restrict__ gamma,
                              const float* __restrict__ beta,
                              const float* __restrict__ rmean,
                              const float* __restrict__ rvar,
                              const float* __restrict__ w2,      // [DIM*KK, CR]
                              const float* __restrict__ b2) {
    const int b = blockIdx.x;
    const int tid = threadIdx.x;   // 128 threads

    __shared__ float pooled_s[DIM];
    __shared__ float h1_s[CR];

    if (tid < DIM) pooled_s[tid] = g_pooled[b * DIM + tid];
    __syncthreads();

    if (tid < CR) {
        float acc = 0.f;
        const float* wrow = w1 + tid * DIM;
#pragma unroll 8
        for (int i = 0; i < DIM; i++) acc += pooled_s[i] * wrow[i];
        float z = (acc - rmean[tid]) * rsqrtf(rvar[tid] + BN_EPS) * gamma[tid] + beta[tid];
        h1_s[tid] = 1.0f / (1.0f + __expf(-z));
    }
    __syncthreads();

    const int nout = DIM * KK;  // 864
    for (int o = tid; o < nout; o += 128) {
        const float* wrow = w2 + o * CR;
        float acc = b2[o];
#pragma unroll
        for (int i = 0; i < CR; i++) acc += h1_s[i] * wrow[i];
        g_wdyn[b * nout + o] = acc;
    }
}

// ---------------------------------------------------------------------------
// Kernel 3: per-sample depthwise 3x3, stride 1, pad 1 — no smem version.
// One WARP per (plane, 32-row chunk): lane tx owns the 4-col strip [4tx,4tx+4).
// Sliding 3-row register window fed directly by coalesced LDG.128; column
// neighbors via 2 SHFLs per row (lane 0/31 edges are the true zero pad).
// Planes processed in REVERSE order so the tail of x, still L2-resident from
// pool_kernel's ascending stream, is read as L2 hits.
// ---------------------------------------------------------------------------
#define CHUNKS 4
#define CHUNK_H (HH / CHUNKS)   // 32

__global__ __launch_bounds__(128) void dwconv_kernel(const float* __restrict__ x,
                                                     const float* __restrict__ bias,
                                                     float* __restrict__ out) {
    const int wid = threadIdx.x >> 5;
    const int tx  = threadIdx.x & 31;
    const int lin = blockIdx.x * 4 + wid;          // 0 .. NPLANES*CHUNKS-1
    const int plane = (NPLANES - 1) - (lin >> 2);  // reversed plane order
    const int chunk = lin & 3;
    const int c = plane % DIM;
    const int r0 = chunk * CHUNK_H;

    const float4* __restrict__ x4  = (const float4*)(x)   + (size_t)plane * PLANE_F4;
    float4*       __restrict__ out4 = (float4*)(out)      + (size_t)plane * PLANE_F4;

    const float* wp = g_wdyn + plane * KK;         // uniform -> broadcast loads
    const float w00 = wp[0], w01 = wp[1], w02 = wp[2];
    const float w10 = wp[3], w11 = wp[4], w12 = wp[5];
    const float w20 = wp[6], w21 = wp[7], w22 = wp[8];
    const float bv = bias[c];

    const float4 zero4 = make_float4(0.f, 0.f, 0.f, 0.f);

    // window rows: A = r-1, B = r, C = r+1 (r = current output row)
    float4 vA = (r0 == 0) ? zero4 : x4[(r0 - 1) * 32 + tx];
    float4 vB = x4[r0 * 32 + tx];
    float lA = __shfl_up_sync(0xffffffffu, vA.w, 1);
    float rA = __shfl_down_sync(0xffffffffu, vA.x, 1);
    float lB = __shfl_up_sync(0xffffffffu, vB.w, 1);
    float rB = __shfl_down_sync(0xffffffffu, vB.x, 1);
    if (tx == 0)  { lA = 0.f; lB = 0.f; }
    if (tx == 31) { rA = 0.f; rB = 0.f; }

#pragma unroll 4
    for (int i = 0; i < CHUNK_H; i++) {
        const int rn = r0 + i + 1;
        float4 vC = (rn < HH) ? x4[rn * 32 + tx] : zero4;
        float lC = __shfl_up_sync(0xffffffffu, vC.w, 1);
        float rC = __shfl_down_sync(0xffffffffu, vC.x, 1);
        if (tx == 0)  lC = 0.f;
        if (tx == 31) rC = 0.f;

        float4 o;
        o.x = bv + w00 * lA   + w01 * vA.x + w02 * vA.y
                 + w10 * lB   + w11 * vB.x + w12 * vB.y
                 + w20 * lC   + w21 * vC.x + w22 * vC.y;
        o.y = bv + w00 * vA.x + w01 * vA.y + w02 * vA.z
                 + w10 * vB.x + w11 * vB.y + w12 * vB.z
                 + w20 * vC.x + w21 * vC.y + w22 * vC.z;
        o.z = bv + w00 * vA.y + w01 * vA.z + w02 * vA.w
                 + w10 * vB.y + w11 * vB.z + w12 * vB.w
                 + w20 * vC.y + w21 * vC.z + w22 * vC.w;
        o.w = bv + w00 * vA.z + w01 * vA.w + w02 * rA
                 + w10 * vB.z + w11 * vB.w + w12 * rB
                 + w20 * vC.z + w21 * vC.w + w22 * rC;

        out4[(r0 + i) * 32 + tx] = o;

        vA = vB; lA = lB; rA = rB;
        vB = vC; lB = lC; rB = rC;
    }
}

// ---------------------------------------------------------------------------
extern "C" void kernel_launch(void* const* d_in, const int* in_sizes, int n_in,
                              void* d_out, int out_size) {
    const float* x     = (const float*)d_in[0];
    const float* w1    = (const float*)d_in[1];
    const float* gamma = (const float*)d_in[2];
    const float* beta  = (const float*)d_in[3];
    const float* rmean = (const float*)d_in[4];
    const float* rvar  = (const float*)d_in[5];
    const float* w2    = (const float*)d_in[6];
    const float* b2    = (const float*)d_in[7];
    const float* bias  = (const float*)d_in[8];
    float* out = (float*)d_out;

    pool_kernel<<<NPLANES, 256>>>(x);
    weight_kernel<<<BATCH, 128>>>(w1, gamma, beta, rmean, rvar, w2, b2);
    dwconv_kernel<<<NPLANES * CHUNKS / 4, 128>>>(x, bias, out);
}